// round 1
// baseline (speedup 1.0000x reference)
#include <cuda_runtime.h>

#define NN 200000
#define DD 128
#define EE 200000
#define EE2 20000
#define SS 6
#define LL 4

// ---------------- device scratch (no allocation allowed) ----------------
__device__ float g_feat[NN * DD];
__device__ float g_res [NN * DD];
__device__ float g_tmp [NN * DD];
__device__ float g_y   [NN * DD];

__device__ __forceinline__ float4 ld4(const float* p) { return *(const float4*)p; }

__device__ __forceinline__ float wsum(float s) {
#pragma unroll
    for (int o = 16; o; o >>= 1) s += __shfl_xor_sync(0xffffffffu, s, o);
    return s;
}

// ---------------- encoder stage 1: h = relu(x @ W1 + b1), x is [N,2] ----------------
__global__ __launch_bounds__(256) void enc1_kernel(
    const float* __restrict__ ctrs, const float* __restrict__ feats,
    const float* __restrict__ w_in1, const float* __restrict__ b_in1,
    const float* __restrict__ w_seg1, const float* __restrict__ b_seg1,
    float* __restrict__ h_in, float* __restrict__ h_seg)
{
    int idx = blockIdx.x * blockDim.x + threadIdx.x;   // one float4 per thread
    int n = idx >> 5;
    if (n >= NN) return;
    int c = (idx & 31) * 4;

    float c0 = __ldg(&ctrs[2 * n]),  c1 = __ldg(&ctrs[2 * n + 1]);
    float f0 = __ldg(&feats[2 * n]), f1 = __ldg(&feats[2 * n + 1]);

    float4 wi0 = ld4(w_in1 + c), wi1 = ld4(w_in1 + DD + c), bi = ld4(b_in1 + c);
    float4 ws0 = ld4(w_seg1 + c), ws1 = ld4(w_seg1 + DD + c), bs = ld4(b_seg1 + c);

    float4 hi, hs;
    hi.x = fmaxf(c0 * wi0.x + c1 * wi1.x + bi.x, 0.f);
    hi.y = fmaxf(c0 * wi0.y + c1 * wi1.y + bi.y, 0.f);
    hi.z = fmaxf(c0 * wi0.z + c1 * wi1.z + bi.z, 0.f);
    hi.w = fmaxf(c0 * wi0.w + c1 * wi1.w + bi.w, 0.f);
    hs.x = fmaxf(f0 * ws0.x + f1 * ws1.x + bs.x, 0.f);
    hs.y = fmaxf(f0 * ws0.y + f1 * ws1.y + bs.y, 0.f);
    hs.z = fmaxf(f0 * ws0.z + f1 * ws1.z + bs.z, 0.f);
    hs.w = fmaxf(f0 * ws0.w + f1 * ws1.w + bs.w, 0.f);

    *(float4*)&h_in [n * DD + c] = hi;
    *(float4*)&h_seg[n * DD + c] = hs;
}

// ---------------- SGEMM: C[N,128] = A[N,128] * B[128,128], row-major ----------------
// BM=64 rows per block, full N=128 cols, BK=32 k-tiles. 256 threads,
// each thread computes 8 rows x 4 cols. FFMA-bound by design.
__global__ __launch_bounds__(256) void gemm128_kernel(
    const float* __restrict__ A, const float* __restrict__ B, float* __restrict__ C)
{
    __shared__ float As[32][64];    // [k][row]  (transposed A tile)
    __shared__ float Bs[32][128];   // [k][col]

    int tid = threadIdx.x;
    int rowBase = blockIdx.x * 64;
    int cg = tid & 31;              // column group -> cols 4*cg..4*cg+3
    int rg = tid >> 5;              // row group   -> rows 8*rg..8*rg+7
    int c0 = cg * 4;

    float acc[8][4];
#pragma unroll
    for (int r = 0; r < 8; r++)
#pragma unroll
        for (int c = 0; c < 4; c++) acc[r][c] = 0.f;

    for (int kt = 0; kt < 128; kt += 32) {
        // load A tile (64x32) transposed: 512 float4, 2 per thread
#pragma unroll
        for (int i = 0; i < 2; i++) {
            int li = tid + i * 256;           // 0..511
            int r  = li >> 3;                 // 0..63
            int kk = (li & 7) * 4;            // 0..28
            float4 a = ld4(&A[(rowBase + r) * 128 + kt + kk]);
            As[kk + 0][r] = a.x; As[kk + 1][r] = a.y;
            As[kk + 2][r] = a.z; As[kk + 3][r] = a.w;
        }
        // load B tile (32x128): 1024 float4, 4 per thread
#pragma unroll
        for (int i = 0; i < 4; i++) {
            int li = tid + i * 256;           // 0..1023
            int kk = li >> 5;                 // 0..31
            int cc = (li & 31) * 4;
            *(float4*)&Bs[kk][cc] = ld4(&B[(kt + kk) * 128 + cc]);
        }
        __syncthreads();

#pragma unroll
        for (int k = 0; k < 32; k++) {
            float4 b4 = *(const float4*)&Bs[k][c0];
            float4 a0 = *(const float4*)&As[k][rg * 8];
            float4 a1 = *(const float4*)&As[k][rg * 8 + 4];
            float ar[8] = {a0.x, a0.y, a0.z, a0.w, a1.x, a1.y, a1.z, a1.w};
#pragma unroll
            for (int r = 0; r < 8; r++) {
                acc[r][0] += ar[r] * b4.x;
                acc[r][1] += ar[r] * b4.y;
                acc[r][2] += ar[r] * b4.z;
                acc[r][3] += ar[r] * b4.w;
            }
        }
        __syncthreads();
    }

#pragma unroll
    for (int r = 0; r < 8; r++) {
        int row = rowBase + rg * 8 + r;
        float4 o = make_float4(acc[r][0], acc[r][1], acc[r][2], acc[r][3]);
        *(float4*)&C[row * 128 + c0] = o;
    }
}

// ---------------- scatter: temp[u] += Y[v] (row add, vector red) ----------------
__global__ __launch_bounds__(256) void scatter_kernel(
    float* __restrict__ temp, const float* __restrict__ Y,
    const int* __restrict__ U, const int* __restrict__ V, int E)
{
    int e = blockIdx.x * 8 + (threadIdx.x >> 5);
    if (e >= E) return;
    int lane = threadIdx.x & 31;
    int u = __ldg(&U[e]);
    int v = __ldg(&V[e]);
    float4 y = ld4(&Y[(long)v * 128 + lane * 4]);
    float* p = &temp[(long)u * 128 + lane * 4];
    asm volatile("red.global.add.v4.f32 [%0], {%1,%2,%3,%4};"
                 :: "l"(p), "f"(y.x), "f"(y.y), "f"(y.z), "f"(y.w) : "memory");
}

// ---------------- GN helpers: one warp per row ----------------
__device__ __forceinline__ void gn_stats(float4 x, float& mean, float& kinv) {
    float s  = x.x + x.y + x.z + x.w;
    float sq = x.x * x.x + x.y * x.y + x.z * x.z + x.w * x.w;
    s  = wsum(s)  * (1.f / 128.f);
    sq = wsum(sq) * (1.f / 128.f);
    mean = s;
    float var = sq - s * s;
    kinv = rsqrtf(var + 1e-5f);
}

// feat = relu(gn(A,gA,bA) + gn(Bv,gB,bB)); res = feat
__global__ __launch_bounds__(256) void enc2_kernel(
    const float* __restrict__ A, const float* __restrict__ gA, const float* __restrict__ bA,
    const float* __restrict__ Bv, const float* __restrict__ gB, const float* __restrict__ bB,
    float* __restrict__ feat, float* __restrict__ res)
{
    int row = blockIdx.x * 8 + (threadIdx.x >> 5);
    if (row >= NN) return;
    int lane = threadIdx.x & 31;
    int c = lane * 4;
    float4 a = ld4(&A[(long)row * 128 + c]);
    float4 b = ld4(&Bv[(long)row * 128 + c]);
    float ma, ka, mb, kb;
    gn_stats(a, ma, ka);
    gn_stats(b, mb, kb);
    float4 ga = ld4(gA + c), ba = ld4(bA + c);
    float4 gb = ld4(gB + c), bb = ld4(bB + c);
    float4 o;
    o.x = fmaxf((a.x - ma) * ka * ga.x + ba.x + (b.x - mb) * kb * gb.x + bb.x, 0.f);
    o.y = fmaxf((a.y - ma) * ka * ga.y + ba.y + (b.y - mb) * kb * gb.y + bb.y, 0.f);
    o.z = fmaxf((a.z - ma) * ka * ga.z + ba.z + (b.z - mb) * kb * gb.z + bb.z, 0.f);
    o.w = fmaxf((a.w - ma) * ka * ga.w + ba.w + (b.w - mb) * kb * gb.w + bb.w, 0.f);
    *(float4*)&feat[(long)row * 128 + c] = o;
    *(float4*)&res [(long)row * 128 + c] = o;
}

// out = relu(gn(X,g,b))
__global__ __launch_bounds__(256) void gn_relu_kernel(
    const float* __restrict__ X, const float* __restrict__ g, const float* __restrict__ b,
    float* __restrict__ out)
{
    int row = blockIdx.x * 8 + (threadIdx.x >> 5);
    if (row >= NN) return;
    int lane = threadIdx.x & 31;
    int c = lane * 4;
    float4 x = ld4(&X[(long)row * 128 + c]);
    float m, k;
    gn_stats(x, m, k);
    float4 gg = ld4(g + c), bb = ld4(b + c);
    float4 o;
    o.x = fmaxf((x.x - m) * k * gg.x + bb.x, 0.f);
    o.y = fmaxf((x.y - m) * k * gg.y + bb.y, 0.f);
    o.z = fmaxf((x.z - m) * k * gg.z + bb.z, 0.f);
    o.w = fmaxf((x.w - m) * k * gg.w + bb.w, 0.f);
    *(float4*)&out[(long)row * 128 + c] = o;
}

// feat = relu(gn(X,g,b) + res_in); res = feat; optional dout = feat
__global__ __launch_bounds__(256) void gn_add_relu_kernel(
    const float* __restrict__ X, const float* __restrict__ g, const float* __restrict__ b,
    float* __restrict__ res, float* __restrict__ feat, float* __restrict__ dout)
{
    int row = blockIdx.x * 8 + (threadIdx.x >> 5);
    if (row >= NN) return;
    int lane = threadIdx.x & 31;
    int c = lane * 4;
    float4 x = ld4(&X[(long)row * 128 + c]);
    float m, k;
    gn_stats(x, m, k);
    float4 gg = ld4(g + c), bb = ld4(b + c);
    float4 r = ld4(&res[(long)row * 128 + c]);
    float4 o;
    o.x = fmaxf((x.x - m) * k * gg.x + bb.x + r.x, 0.f);
    o.y = fmaxf((x.y - m) * k * gg.y + bb.y + r.y, 0.f);
    o.z = fmaxf((x.z - m) * k * gg.z + bb.z + r.z, 0.f);
    o.w = fmaxf((x.w - m) * k * gg.w + bb.w + r.w, 0.f);
    *(float4*)&feat[(long)row * 128 + c] = o;
    *(float4*)&res [(long)row * 128 + c] = o;
    if (dout) *(float4*)&dout[(long)row * 128 + c] = o;
}

// ---------------- host launcher ----------------
extern "C" void kernel_launch(void* const* d_in, const int* in_sizes, int n_in,
                              void* d_out, int out_size)
{
    const float* ctrs   = (const float*)d_in[0];
    const float* feats  = (const float*)d_in[1];
    const float* w_in1  = (const float*)d_in[2];
    const float* b_in1  = (const float*)d_in[3];
    const float* w_in2  = (const float*)d_in[4];
    const float* g_in   = (const float*)d_in[5];
    const float* be_in  = (const float*)d_in[6];
    const float* w_seg1 = (const float*)d_in[7];
    const float* b_seg1 = (const float*)d_in[8];
    const float* w_seg2 = (const float*)d_in[9];
    const float* g_seg  = (const float*)d_in[10];
    const float* be_seg = (const float*)d_in[11];
    const float* ctr_w  = (const float*)d_in[12];   // [L,128,128]
    const float* pre_w  = (const float*)d_in[13];   // [L,S,128,128]
    const float* suc_w  = (const float*)d_in[14];   // [L,S,128,128]
    const float* left_w = (const float*)d_in[15];   // [L,128,128]
    const float* right_w= (const float*)d_in[16];   // [L,128,128]
    const float* norm_g = (const float*)d_in[17];   // [L,128]
    const float* norm_b = (const float*)d_in[18];
    const float* ctr2_w = (const float*)d_in[19];   // [L,128,128]
    const float* ctr2_g = (const float*)d_in[20];
    const float* ctr2_b = (const float*)d_in[21];
    const int* pre_u  = (const int*)d_in[22];       // [S,E]
    const int* pre_v  = (const int*)d_in[23];
    const int* suc_u  = (const int*)d_in[24];
    const int* suc_v  = (const int*)d_in[25];
    const int* left_u = (const int*)d_in[26];
    const int* left_v = (const int*)d_in[27];
    const int* right_u= (const int*)d_in[28];
    const int* right_v= (const int*)d_in[29];

    float *feat, *res, *tmp, *y;
    cudaGetSymbolAddress((void**)&feat, g_feat);
    cudaGetSymbolAddress((void**)&res,  g_res);
    cudaGetSymbolAddress((void**)&tmp,  g_tmp);
    cudaGetSymbolAddress((void**)&y,    g_y);

    const int GN_BLOCKS   = NN / 8;          // 25000
    const int GEMM_BLOCKS = NN / 64;         // 3125
    const int SC_BLOCKS   = (EE + 7) / 8;    // 25000
    const int SC2_BLOCKS  = (EE2 + 7) / 8;   // 2500
    const int MAT = 128 * 128;

    // ---- encoders ----
    enc1_kernel<<<(NN * 32) / 256, 256>>>(ctrs, feats, w_in1, b_in1, w_seg1, b_seg1, tmp, y);
    gemm128_kernel<<<GEMM_BLOCKS, 256>>>(tmp, w_in2, res);
    gemm128_kernel<<<GEMM_BLOCKS, 256>>>(y,   w_seg2, feat);
    enc2_kernel<<<GN_BLOCKS, 256>>>(res, g_in, be_in, feat, g_seg, be_seg, feat, res);

    // ---- fuse loop ----
    for (int i = 0; i < LL; i++) {
        gemm128_kernel<<<GEMM_BLOCKS, 256>>>(feat, ctr_w + i * MAT, tmp);
        for (int s = 0; s < SS; s++) {
            gemm128_kernel<<<GEMM_BLOCKS, 256>>>(feat, pre_w + (i * SS + s) * MAT, y);
            scatter_kernel<<<SC_BLOCKS, 256>>>(tmp, y, pre_u + s * EE, pre_v + s * EE, EE);
            gemm128_kernel<<<GEMM_BLOCKS, 256>>>(feat, suc_w + (i * SS + s) * MAT, y);
            scatter_kernel<<<SC_BLOCKS, 256>>>(tmp, y, suc_u + s * EE, suc_v + s * EE, EE);
        }
        gemm128_kernel<<<GEMM_BLOCKS, 256>>>(feat, left_w + i * MAT, y);
        scatter_kernel<<<SC2_BLOCKS, 256>>>(tmp, y, left_u, left_v, EE2);
        gemm128_kernel<<<GEMM_BLOCKS, 256>>>(feat, right_w + i * MAT, y);
        scatter_kernel<<<SC2_BLOCKS, 256>>>(tmp, y, right_u, right_v, EE2);

        gn_relu_kernel<<<GN_BLOCKS, 256>>>(tmp, norm_g + i * 128, norm_b + i * 128, y);
        gemm128_kernel<<<GEMM_BLOCKS, 256>>>(y, ctr2_w + i * MAT, tmp);
        gn_add_relu_kernel<<<GN_BLOCKS, 256>>>(
            tmp, ctr2_g + i * 128, ctr2_b + i * 128, res, feat,
            (i == LL - 1) ? (float*)d_out : nullptr);
    }
}

// round 2
// speedup vs baseline: 1.5469x; 1.5469x over previous
#include <cuda_runtime.h>
#include <cstdint>

#define NN 200000
#define NPAD 200064     // 1563 * 128, so GEMM needs no row guards
#define DD 128
#define EE 200000
#define EE2 20000
#define SS 6
#define LL 4
#define NBLK 1563
#define ASTR 136        // smem stride (floats): 136 mod 32 == 8 -> conflict-free frags

// ---------------- device scratch (no allocation allowed) ----------------
__device__ float g_feat[NPAD * DD];
__device__ float g_res [NPAD * DD];
__device__ float g_tmp [NPAD * DD];
__device__ float g_y   [NPAD * DD];

__device__ __forceinline__ float4 ld4(const float* p) { return *(const float4*)(p); }

__device__ __forceinline__ float tf32r(float x) {
    float y;
    asm("cvt.rna.tf32.f32 %0, %1;" : "=f"(y) : "f"(x));
    return y;
}

__device__ __forceinline__ float wsum(float s) {
#pragma unroll
    for (int o = 16; o; o >>= 1) s += __shfl_xor_sync(0xffffffffu, s, o);
    return s;
}

// ---------------- encoder stage 1 ----------------
__global__ __launch_bounds__(256) void enc1_kernel(
    const float* __restrict__ ctrs, const float* __restrict__ feats,
    const float* __restrict__ w_in1, const float* __restrict__ b_in1,
    const float* __restrict__ w_seg1, const float* __restrict__ b_seg1,
    float* __restrict__ h_in, float* __restrict__ h_seg)
{
    int idx = blockIdx.x * blockDim.x + threadIdx.x;
    int n = idx >> 5;
    if (n >= NN) return;
    int c = (idx & 31) * 4;

    float c0 = __ldg(&ctrs[2 * n]),  c1 = __ldg(&ctrs[2 * n + 1]);
    float f0 = __ldg(&feats[2 * n]), f1 = __ldg(&feats[2 * n + 1]);

    float4 wi0 = ld4(w_in1 + c), wi1 = ld4(w_in1 + DD + c), bi = ld4(b_in1 + c);
    float4 ws0 = ld4(w_seg1 + c), ws1 = ld4(w_seg1 + DD + c), bs = ld4(b_seg1 + c);

    float4 hi, hs;
    hi.x = fmaxf(c0 * wi0.x + c1 * wi1.x + bi.x, 0.f);
    hi.y = fmaxf(c0 * wi0.y + c1 * wi1.y + bi.y, 0.f);
    hi.z = fmaxf(c0 * wi0.z + c1 * wi1.z + bi.z, 0.f);
    hi.w = fmaxf(c0 * wi0.w + c1 * wi1.w + bi.w, 0.f);
    hs.x = fmaxf(f0 * ws0.x + f1 * ws1.x + bs.x, 0.f);
    hs.y = fmaxf(f0 * ws0.y + f1 * ws1.y + bs.y, 0.f);
    hs.z = fmaxf(f0 * ws0.z + f1 * ws1.z + bs.z, 0.f);
    hs.w = fmaxf(f0 * ws0.w + f1 * ws1.w + bs.w, 0.f);

    *(float4*)&h_in [n * DD + c] = hi;
    *(float4*)&h_seg[n * DD + c] = hs;
}

// ---------------- TF32 tensor-core GEMM: C[NPAD,128] = A[NPAD,128] @ B[128,128] ----------------
// Block: 128 rows x 128 cols, 256 threads = 8 warps (4m x 2n). Warp tile 32x64.
// mma.sync m16n8k8 tf32. B fully resident in smem; A chunked by K=32.
__global__ __launch_bounds__(256, 2) void gemm_tf32_kernel(
    const float* __restrict__ A, const float* __restrict__ B, float* __restrict__ C)
{
    extern __shared__ float sm[];
    float* Bs = sm;                  // [128][ASTR]  (k-major rows: Bs[k][n])
    float* As = sm + 128 * ASTR;     // [32][ASTR]   (k-major: As[k][row])

    int tid  = threadIdx.x;
    int lane = tid & 31;
    int warp = tid >> 5;
    int gid = lane >> 2, tig = lane & 3;
    int wm = warp >> 1, wn = warp & 1;
    long rowBase = (long)blockIdx.x * 128;

    // Load B fully (128x128) with tf32 rounding. 16 float4 per thread.
    for (int i = tid; i < 128 * 32; i += 256) {
        int r = i >> 5, c = (i & 31) * 4;
        float4 b = ld4(B + r * 128 + c);
        float* d = Bs + r * ASTR + c;
        d[0] = tf32r(b.x); d[1] = tf32r(b.y); d[2] = tf32r(b.z); d[3] = tf32r(b.w);
    }

    float acc[2][8][4];
#pragma unroll
    for (int tm = 0; tm < 2; tm++)
#pragma unroll
        for (int nt = 0; nt < 8; nt++)
#pragma unroll
            for (int j = 0; j < 4; j++) acc[tm][nt][j] = 0.f;

    int lr  = tid >> 1;           // load row within block: 0..127
    int lkh = (tid & 1) * 16;     // k half within chunk

    for (int kt = 0; kt < 128; kt += 32) {
        // Load A chunk (128 rows x 32 k) transposed into As[k][row]
        const float* ap = A + (rowBase + lr) * 128 + kt + lkh;
#pragma unroll
        for (int j = 0; j < 4; j++) {
            float4 a = ld4(ap + j * 4);
            int k0 = lkh + j * 4;
            As[(k0 + 0) * ASTR + lr] = tf32r(a.x);
            As[(k0 + 1) * ASTR + lr] = tf32r(a.y);
            As[(k0 + 2) * ASTR + lr] = tf32r(a.z);
            As[(k0 + 3) * ASTR + lr] = tf32r(a.w);
        }
        __syncthreads();

#pragma unroll
        for (int ks = 0; ks < 4; ks++) {
            uint32_t af[2][4];
#pragma unroll
            for (int tm = 0; tm < 2; tm++) {
                int rr = wm * 32 + tm * 16 + gid;
                const float* a0p = As + (ks * 8 + tig) * ASTR + rr;
                const float* a1p = As + (ks * 8 + tig + 4) * ASTR + rr;
                af[tm][0] = __float_as_uint(a0p[0]);
                af[tm][1] = __float_as_uint(a0p[8]);
                af[tm][2] = __float_as_uint(a1p[0]);
                af[tm][3] = __float_as_uint(a1p[8]);
            }
#pragma unroll
            for (int nt = 0; nt < 8; nt++) {
                int cc = wn * 64 + nt * 8 + gid;
                uint32_t b0 = __float_as_uint(Bs[(kt + ks * 8 + tig) * ASTR + cc]);
                uint32_t b1 = __float_as_uint(Bs[(kt + ks * 8 + tig + 4) * ASTR + cc]);
#pragma unroll
                for (int tm = 0; tm < 2; tm++) {
                    asm volatile(
                        "mma.sync.aligned.m16n8k8.row.col.f32.tf32.tf32.f32 "
                        "{%0,%1,%2,%3}, {%4,%5,%6,%7}, {%8,%9}, {%0,%1,%2,%3};\n"
                        : "+f"(acc[tm][nt][0]), "+f"(acc[tm][nt][1]),
                          "+f"(acc[tm][nt][2]), "+f"(acc[tm][nt][3])
                        : "r"(af[tm][0]), "r"(af[tm][1]), "r"(af[tm][2]), "r"(af[tm][3]),
                          "r"(b0), "r"(b1));
                }
            }
        }
        __syncthreads();
    }

    // Epilogue: direct float2 stores (c0,c1)/(c2,c3)
#pragma unroll
    for (int tm = 0; tm < 2; tm++) {
        long r0 = rowBase + wm * 32 + tm * 16 + gid;
#pragma unroll
        for (int nt = 0; nt < 8; nt++) {
            int cc = wn * 64 + nt * 8 + tig * 2;
            *(float2*)(C + r0 * 128 + cc)       = make_float2(acc[tm][nt][0], acc[tm][nt][1]);
            *(float2*)(C + (r0 + 8) * 128 + cc) = make_float2(acc[tm][nt][2], acc[tm][nt][3]);
        }
    }
}

// ---------------- scatter: temp[u] += Y[v] ----------------
__global__ __launch_bounds__(256) void scatter_kernel(
    float* __restrict__ temp, const float* __restrict__ Y,
    const int* __restrict__ U, const int* __restrict__ V, int E)
{
    int e = blockIdx.x * 8 + (threadIdx.x >> 5);
    if (e >= E) return;
    int lane = threadIdx.x & 31;
    int u = __ldg(&U[e]);
    int v = __ldg(&V[e]);
    float4 y = ld4(&Y[(long)v * 128 + lane * 4]);
    float* p = &temp[(long)u * 128 + lane * 4];
    asm volatile("red.global.add.v4.f32 [%0], {%1,%2,%3,%4};"
                 :: "l"(p), "f"(y.x), "f"(y.y), "f"(y.z), "f"(y.w) : "memory");
}

// ---------------- GN helpers ----------------
__device__ __forceinline__ void gn_stats(float4 x, float& mean, float& kinv) {
    float s  = x.x + x.y + x.z + x.w;
    float sq = x.x * x.x + x.y * x.y + x.z * x.z + x.w * x.w;
    s  = wsum(s)  * (1.f / 128.f);
    sq = wsum(sq) * (1.f / 128.f);
    mean = s;
    float var = sq - s * s;
    kinv = rsqrtf(var + 1e-5f);
}

__global__ __launch_bounds__(256) void enc2_kernel(
    const float* __restrict__ A, const float* __restrict__ gA, const float* __restrict__ bA,
    const float* __restrict__ Bv, const float* __restrict__ gB, const float* __restrict__ bB,
    float* __restrict__ feat, float* __restrict__ res)
{
    int row = blockIdx.x * 8 + (threadIdx.x >> 5);
    if (row >= NN) return;
    int lane = threadIdx.x & 31;
    int c = lane * 4;
    float4 a = ld4(&A[(long)row * 128 + c]);
    float4 b = ld4(&Bv[(long)row * 128 + c]);
    float ma, ka, mb, kb;
    gn_stats(a, ma, ka);
    gn_stats(b, mb, kb);
    float4 ga = ld4(gA + c), ba = ld4(bA + c);
    float4 gb = ld4(gB + c), bb = ld4(bB + c);
    float4 o;
    o.x = fmaxf((a.x - ma) * ka * ga.x + ba.x + (b.x - mb) * kb * gb.x + bb.x, 0.f);
    o.y = fmaxf((a.y - ma) * ka * ga.y + ba.y + (b.y - mb) * kb * gb.y + bb.y, 0.f);
    o.z = fmaxf((a.z - ma) * ka * ga.z + ba.z + (b.z - mb) * kb * gb.z + bb.z, 0.f);
    o.w = fmaxf((a.w - ma) * ka * ga.w + ba.w + (b.w - mb) * kb * gb.w + bb.w, 0.f);
    *(float4*)&feat[(long)row * 128 + c] = o;
    *(float4*)&res [(long)row * 128 + c] = o;
}

__global__ __launch_bounds__(256) void gn_relu_kernel(
    const float* __restrict__ X, const float* __restrict__ g, const float* __restrict__ b,
    float* __restrict__ out)
{
    int row = blockIdx.x * 8 + (threadIdx.x >> 5);
    if (row >= NN) return;
    int lane = threadIdx.x & 31;
    int c = lane * 4;
    float4 x = ld4(&X[(long)row * 128 + c]);
    float m, k;
    gn_stats(x, m, k);
    float4 gg = ld4(g + c), bb = ld4(b + c);
    float4 o;
    o.x = fmaxf((x.x - m) * k * gg.x + bb.x, 0.f);
    o.y = fmaxf((x.y - m) * k * gg.y + bb.y, 0.f);
    o.z = fmaxf((x.z - m) * k * gg.z + bb.z, 0.f);
    o.w = fmaxf((x.w - m) * k * gg.w + bb.w, 0.f);
    *(float4*)&out[(long)row * 128 + c] = o;
}

__global__ __launch_bounds__(256) void gn_add_relu_kernel(
    const float* __restrict__ X, const float* __restrict__ g, const float* __restrict__ b,
    float* __restrict__ res, float* __restrict__ feat, float* __restrict__ dout)
{
    int row = blockIdx.x * 8 + (threadIdx.x >> 5);
    if (row >= NN) return;
    int lane = threadIdx.x & 31;
    int c = lane * 4;
    float4 x = ld4(&X[(long)row * 128 + c]);
    float m, k;
    gn_stats(x, m, k);
    float4 gg = ld4(g + c), bb = ld4(b + c);
    float4 r = ld4(&res[(long)row * 128 + c]);
    float4 o;
    o.x = fmaxf((x.x - m) * k * gg.x + bb.x + r.x, 0.f);
    o.y = fmaxf((x.y - m) * k * gg.y + bb.y + r.y, 0.f);
    o.z = fmaxf((x.z - m) * k * gg.z + bb.z + r.z, 0.f);
    o.w = fmaxf((x.w - m) * k * gg.w + bb.w + r.w, 0.f);
    *(float4*)&feat[(long)row * 128 + c] = o;
    *(float4*)&res [(long)row * 128 + c] = o;
    if (dout) *(float4*)&dout[(long)row * 128 + c] = o;
}

// ---------------- host launcher ----------------
extern "C" void kernel_launch(void* const* d_in, const int* in_sizes, int n_in,
                              void* d_out, int out_size)
{
    const float* ctrs   = (const float*)d_in[0];
    const float* feats  = (const float*)d_in[1];
    const float* w_in1  = (const float*)d_in[2];
    const float* b_in1  = (const float*)d_in[3];
    const float* w_in2  = (const float*)d_in[4];
    const float* g_in   = (const float*)d_in[5];
    const float* be_in  = (const float*)d_in[6];
    const float* w_seg1 = (const float*)d_in[7];
    const float* b_seg1 = (const float*)d_in[8];
    const float* w_seg2 = (const float*)d_in[9];
    const float* g_seg  = (const float*)d_in[10];
    const float* be_seg = (const float*)d_in[11];
    const float* ctr_w  = (const float*)d_in[12];
    const float* pre_w  = (const float*)d_in[13];
    const float* suc_w  = (const float*)d_in[14];
    const float* left_w = (const float*)d_in[15];
    const float* right_w= (const float*)d_in[16];
    const float* norm_g = (const float*)d_in[17];
    const float* norm_b = (const float*)d_in[18];
    const float* ctr2_w = (const float*)d_in[19];
    const float* ctr2_g = (const float*)d_in[20];
    const float* ctr2_b = (const float*)d_in[21];
    const int* pre_u  = (const int*)d_in[22];
    const int* pre_v  = (const int*)d_in[23];
    const int* suc_u  = (const int*)d_in[24];
    const int* suc_v  = (const int*)d_in[25];
    const int* left_u = (const int*)d_in[26];
    const int* left_v = (const int*)d_in[27];
    const int* right_u= (const int*)d_in[28];
    const int* right_v= (const int*)d_in[29];

    float *feat, *res, *tmp, *y;
    cudaGetSymbolAddress((void**)&feat, g_feat);
    cudaGetSymbolAddress((void**)&res,  g_res);
    cudaGetSymbolAddress((void**)&tmp,  g_tmp);
    cudaGetSymbolAddress((void**)&y,    g_y);

    const int GN_BLOCKS  = NN / 8;
    const int SC_BLOCKS  = (EE + 7) / 8;
    const int SC2_BLOCKS = (EE2 + 7) / 8;
    const int MAT = 128 * 128;
    const int SMEM = (128 + 32) * ASTR * 4;  // 87040 bytes

    static bool attr_set = false;
    if (!attr_set) {
        cudaFuncSetAttribute(gemm_tf32_kernel,
                             cudaFuncAttributeMaxDynamicSharedMemorySize, SMEM);
        attr_set = true;
    }

    // ---- encoders ----
    enc1_kernel<<<(NN * 32) / 256, 256>>>(ctrs, feats, w_in1, b_in1, w_seg1, b_seg1, tmp, y);
    gemm_tf32_kernel<<<NBLK, 256, SMEM>>>(tmp, w_in2, res);
    gemm_tf32_kernel<<<NBLK, 256, SMEM>>>(y,   w_seg2, feat);
    enc2_kernel<<<GN_BLOCKS, 256>>>(res, g_in, be_in, feat, g_seg, be_seg, feat, res);

    // ---- fuse loop ----
    for (int i = 0; i < LL; i++) {
        gemm_tf32_kernel<<<NBLK, 256, SMEM>>>(feat, ctr_w + i * MAT, tmp);
        for (int s = 0; s < SS; s++) {
            gemm_tf32_kernel<<<NBLK, 256, SMEM>>>(feat, pre_w + (i * SS + s) * MAT, y);
            scatter_kernel<<<SC_BLOCKS, 256>>>(tmp, y, pre_u + s * EE, pre_v + s * EE, EE);
            gemm_tf32_kernel<<<NBLK, 256, SMEM>>>(feat, suc_w + (i * SS + s) * MAT, y);
            scatter_kernel<<<SC_BLOCKS, 256>>>(tmp, y, suc_u + s * EE, suc_v + s * EE, EE);
        }
        gemm_tf32_kernel<<<NBLK, 256, SMEM>>>(feat, left_w + i * MAT, y);
        scatter_kernel<<<SC2_BLOCKS, 256>>>(tmp, y, left_u, left_v, EE2);
        gemm_tf32_kernel<<<NBLK, 256, SMEM>>>(feat, right_w + i * MAT, y);
        scatter_kernel<<<SC2_BLOCKS, 256>>>(tmp, y, right_u, right_v, EE2);

        gn_relu_kernel<<<GN_BLOCKS, 256>>>(tmp, norm_g + i * 128, norm_b + i * 128, y);
        gemm_tf32_kernel<<<NBLK, 256, SMEM>>>(y, ctr2_w + i * MAT, tmp);
        gn_add_relu_kernel<<<GN_BLOCKS, 256>>>(
            tmp, ctr2_g + i * 128, ctr2_b + i * 128, res, feat,
            (i == LL - 1) ? (float*)d_out : nullptr);
    }
}

// round 3
// speedup vs baseline: 2.3020x; 1.4881x over previous
#include <cuda_runtime.h>
#include <cstdint>

#define NN 200000
#define NPAD 200064     // 1563 * 128
#define DD 128
#define EE 200000
#define EE2 20000
#define SS 6
#define LL 4
#define NBLK 1563
#define ASTR 136        // smem stride (floats), 136 mod 32 == 8 -> conflict-free frags
#define NTYPE 14        // scatter types: pre0-5, suc0-5, left, right
#define NBUCK (NTYPE * NBLK)
#define TOTAL_E (12 * EE + 2 * EE2)

// ---------------- device scratch ----------------
__device__ float g_feat[NPAD * DD];
__device__ float g_tmp [NPAD * DD];
__device__ float g_y   [NPAD * DD];
__device__ int   g_cnt [NBUCK];
__device__ int   g_cur [NBUCK];
__device__ int   g_bptr[NBUCK + 1];
__device__ int   g_edges[TOTAL_E];

__device__ __forceinline__ float4 ld4(const float* p) { return *(const float4*)(p); }

__device__ __forceinline__ float tf32r(float x) {
    float y;
    asm("cvt.rna.tf32.f32 %0, %1;" : "=f"(y) : "f"(x));
    return y;
}

__device__ __forceinline__ float wsum(float s) {
#pragma unroll
    for (int o = 16; o; o >>= 1) s += __shfl_xor_sync(0xffffffffu, s, o);
    return s;
}

__device__ __forceinline__ void redv4(float* p, float4 y) {
    asm volatile("red.global.add.v4.f32 [%0], {%1,%2,%3,%4};"
                 :: "l"(p), "f"(y.x), "f"(y.y), "f"(y.z), "f"(y.w) : "memory");
}

// ---------------- bucket build ----------------
__global__ void count_kernel(const int* __restrict__ pre_v, const int* __restrict__ suc_v,
                             const int* __restrict__ left_v, const int* __restrict__ right_v)
{
    int idx = blockIdx.x * 256 + threadIdx.x;
    int t, v;
    if (idx < 6 * EE)            { t = idx / EE; v = pre_v[idx]; }
    else if (idx < 12 * EE)      { t = idx / EE; v = suc_v[idx - 6 * EE]; }
    else if (idx < 12 * EE + EE2){ t = 12; v = left_v[idx - 12 * EE]; }
    else if (idx < TOTAL_E)      { t = 13; v = right_v[idx - 12 * EE - EE2]; }
    else return;
    atomicAdd(&g_cnt[t * NBLK + (v >> 7)], 1);
}

__global__ void scan_kernel()
{
    __shared__ int sh[1024];
    __shared__ int sbase;
    int tid = threadIdx.x;
    if (tid == 0) sbase = 0;
    __syncthreads();
    for (int c = 0; c < NBUCK; c += 1024) {
        int x = (c + tid < NBUCK) ? g_cnt[c + tid] : 0;
        sh[tid] = x;
        __syncthreads();
        for (int off = 1; off < 1024; off <<= 1) {
            int v = (tid >= off) ? sh[tid - off] : 0;
            __syncthreads();
            sh[tid] += v;
            __syncthreads();
        }
        int base = sbase;
        if (c + tid < NBUCK) g_bptr[c + tid] = base + sh[tid] - x;
        __syncthreads();
        if (tid == 0) sbase = base + sh[1023];
        __syncthreads();
    }
    if (tid == 0) g_bptr[NBUCK] = sbase;
}

__global__ void place_kernel(const int* __restrict__ pre_u, const int* __restrict__ pre_v,
                             const int* __restrict__ suc_u, const int* __restrict__ suc_v,
                             const int* __restrict__ left_u, const int* __restrict__ left_v,
                             const int* __restrict__ right_u, const int* __restrict__ right_v)
{
    int idx = blockIdx.x * 256 + threadIdx.x;
    int t, u, v;
    if (idx < 6 * EE)            { t = idx / EE; u = pre_u[idx]; v = pre_v[idx]; }
    else if (idx < 12 * EE)      { int j = idx - 6 * EE; t = idx / EE; u = suc_u[j]; v = suc_v[j]; }
    else if (idx < 12 * EE + EE2){ int j = idx - 12 * EE; t = 12; u = left_u[j]; v = left_v[j]; }
    else if (idx < TOTAL_E)      { int j = idx - 12 * EE - EE2; t = 13; u = right_u[j]; v = right_v[j]; }
    else return;
    int b = t * NBLK + (v >> 7);
    int pos = g_bptr[b] + atomicAdd(&g_cur[b], 1);
    g_edges[pos] = u | ((v & 127) << 18);
}

// ---------------- encoder stage 1 ----------------
__global__ __launch_bounds__(256) void enc1_kernel(
    const float* __restrict__ ctrs, const float* __restrict__ feats,
    const float* __restrict__ w_in1, const float* __restrict__ b_in1,
    const float* __restrict__ w_seg1, const float* __restrict__ b_seg1,
    float* __restrict__ h_in, float* __restrict__ h_seg)
{
    int idx = blockIdx.x * blockDim.x + threadIdx.x;
    int n = idx >> 5;
    if (n >= NN) return;
    int c = (idx & 31) * 4;

    float c0 = __ldg(&ctrs[2 * n]),  c1 = __ldg(&ctrs[2 * n + 1]);
    float f0 = __ldg(&feats[2 * n]), f1 = __ldg(&feats[2 * n + 1]);

    float4 wi0 = ld4(w_in1 + c), wi1 = ld4(w_in1 + DD + c), bi = ld4(b_in1 + c);
    float4 ws0 = ld4(w_seg1 + c), ws1 = ld4(w_seg1 + DD + c), bs = ld4(b_seg1 + c);

    float4 hi, hs;
    hi.x = fmaxf(c0 * wi0.x + c1 * wi1.x + bi.x, 0.f);
    hi.y = fmaxf(c0 * wi0.y + c1 * wi1.y + bi.y, 0.f);
    hi.z = fmaxf(c0 * wi0.z + c1 * wi1.z + bi.z, 0.f);
    hi.w = fmaxf(c0 * wi0.w + c1 * wi1.w + bi.w, 0.f);
    hs.x = fmaxf(f0 * ws0.x + f1 * ws1.x + bs.x, 0.f);
    hs.y = fmaxf(f0 * ws0.y + f1 * ws1.y + bs.y, 0.f);
    hs.z = fmaxf(f0 * ws0.z + f1 * ws1.z + bs.z, 0.f);
    hs.w = fmaxf(f0 * ws0.w + f1 * ws1.w + bs.w, 0.f);

    *(float4*)&h_in [n * DD + c] = hi;
    *(float4*)&h_seg[n * DD + c] = hs;
}

// ---------------- standalone TF32 GEMM (encoder) ----------------
__global__ __launch_bounds__(256, 2) void gemm_tf32_kernel(
    const float* __restrict__ A, const float* __restrict__ B, float* __restrict__ C)
{
    extern __shared__ float sm[];
    float* Bs = sm;                  // [128][ASTR]
    float* As = sm + 128 * ASTR;     // [32][ASTR]

    int tid  = threadIdx.x;
    int lane = tid & 31;
    int warp = tid >> 5;
    int gid = lane >> 2, tig = lane & 3;
    int wm = warp >> 1, wn = warp & 1;
    long rowBase = (long)blockIdx.x * 128;

    for (int i = tid; i < 128 * 32; i += 256) {
        int r = i >> 5, c = (i & 31) * 4;
        float4 b = ld4(B + r * 128 + c);
        float* d = Bs + r * ASTR + c;
        d[0] = tf32r(b.x); d[1] = tf32r(b.y); d[2] = tf32r(b.z); d[3] = tf32r(b.w);
    }

    float acc[2][8][4];
#pragma unroll
    for (int tm = 0; tm < 2; tm++)
#pragma unroll
        for (int nt = 0; nt < 8; nt++)
#pragma unroll
            for (int j = 0; j < 4; j++) acc[tm][nt][j] = 0.f;

    int lr  = tid >> 1;
    int lkh = (tid & 1) * 16;

    for (int kt = 0; kt < 128; kt += 32) {
        const float* ap = A + (rowBase + lr) * 128 + kt + lkh;
#pragma unroll
        for (int j = 0; j < 4; j++) {
            float4 a = ld4(ap + j * 4);
            int k0 = lkh + j * 4;
            As[(k0 + 0) * ASTR + lr] = tf32r(a.x);
            As[(k0 + 1) * ASTR + lr] = tf32r(a.y);
            As[(k0 + 2) * ASTR + lr] = tf32r(a.z);
            As[(k0 + 3) * ASTR + lr] = tf32r(a.w);
        }
        __syncthreads();

#pragma unroll
        for (int ks = 0; ks < 4; ks++) {
            uint32_t af[2][4];
#pragma unroll
            for (int tm = 0; tm < 2; tm++) {
                int rr = wm * 32 + tm * 16 + gid;
                const float* a0p = As + (ks * 8 + tig) * ASTR + rr;
                const float* a1p = As + (ks * 8 + tig + 4) * ASTR + rr;
                af[tm][0] = __float_as_uint(a0p[0]);
                af[tm][1] = __float_as_uint(a0p[8]);
                af[tm][2] = __float_as_uint(a1p[0]);
                af[tm][3] = __float_as_uint(a1p[8]);
            }
#pragma unroll
            for (int nt = 0; nt < 8; nt++) {
                int cc = wn * 64 + nt * 8 + gid;
                uint32_t b0 = __float_as_uint(Bs[(kt + ks * 8 + tig) * ASTR + cc]);
                uint32_t b1 = __float_as_uint(Bs[(kt + ks * 8 + tig + 4) * ASTR + cc]);
#pragma unroll
                for (int tm = 0; tm < 2; tm++) {
                    asm volatile(
                        "mma.sync.aligned.m16n8k8.row.col.f32.tf32.tf32.f32 "
                        "{%0,%1,%2,%3}, {%4,%5,%6,%7}, {%8,%9}, {%0,%1,%2,%3};\n"
                        : "+f"(acc[tm][nt][0]), "+f"(acc[tm][nt][1]),
                          "+f"(acc[tm][nt][2]), "+f"(acc[tm][nt][3])
                        : "r"(af[tm][0]), "r"(af[tm][1]), "r"(af[tm][2]), "r"(af[tm][3]),
                          "r"(b0), "r"(b1));
                }
            }
        }
        __syncthreads();
    }

#pragma unroll
    for (int tm = 0; tm < 2; tm++) {
        long r0 = rowBase + wm * 32 + tm * 16 + gid;
#pragma unroll
        for (int nt = 0; nt < 8; nt++) {
            int cc = wn * 64 + nt * 8 + tig * 2;
            *(float2*)(C + r0 * 128 + cc)       = make_float2(acc[tm][nt][0], acc[tm][nt][1]);
            *(float2*)(C + (r0 + 8) * 128 + cc) = make_float2(acc[tm][nt][2], acc[tm][nt][3]);
        }
    }
}

// ---------------- encoder stage 2: feat = relu(gn(A) + gn(B)) ----------------
__device__ __forceinline__ void gn_stats(float4 x, float& mean, float& kinv) {
    float s  = x.x + x.y + x.z + x.w;
    float sq = x.x * x.x + x.y * x.y + x.z * x.z + x.w * x.w;
    s  = wsum(s)  * (1.f / 128.f);
    sq = wsum(sq) * (1.f / 128.f);
    mean = s;
    float var = sq - s * s;
    kinv = rsqrtf(var + 1e-5f);
}

__global__ __launch_bounds__(256) void enc2_kernel(
    const float* __restrict__ A, const float* __restrict__ gA, const float* __restrict__ bA,
    const float* __restrict__ Bv, const float* __restrict__ gB, const float* __restrict__ bB,
    float* __restrict__ feat)
{
    int row = blockIdx.x * 8 + (threadIdx.x >> 5);
    if (row >= NN) return;
    int lane = threadIdx.x & 31;
    int c = lane * 4;
    float4 a = ld4(&A[(long)row * 128 + c]);
    float4 b = ld4(&Bv[(long)row * 128 + c]);
    float ma, ka, mb, kb;
    gn_stats(a, ma, ka);
    gn_stats(b, mb, kb);
    float4 ga = ld4(gA + c), ba = ld4(bA + c);
    float4 gb = ld4(gB + c), bb = ld4(bB + c);
    float4 o;
    o.x = fmaxf((a.x - ma) * ka * ga.x + ba.x + (b.x - mb) * kb * gb.x + bb.x, 0.f);
    o.y = fmaxf((a.y - ma) * ka * ga.y + ba.y + (b.y - mb) * kb * gb.y + bb.y, 0.f);
    o.z = fmaxf((a.z - ma) * ka * ga.z + ba.z + (b.z - mb) * kb * gb.z + bb.z, 0.f);
    o.w = fmaxf((a.w - ma) * ka * ga.w + ba.w + (b.w - mb) * kb * gb.w + bb.w, 0.f);
    *(float4*)&feat[(long)row * 128 + c] = o;
}

// ---------------- fused message-passing kernel ----------------
// Per block: load feat tile (128 rows) once; for 15 weight types:
// load B from L2, mma, stage C in smem, scatter-add straight to temp.
__global__ __launch_bounds__(256) void fuse_kernel(
    const float* __restrict__ feat, float* __restrict__ temp,
    const float* __restrict__ pre_w, const float* __restrict__ suc_w,
    const float* __restrict__ left_w, const float* __restrict__ right_w,
    const float* __restrict__ ctr_w)
{
    extern __shared__ float sm[];
    float* As = sm;                       // [128 k][ASTR rows]
    float* Bs = sm + 128 * ASTR;          // [128 k][ASTR cols]
    float* Cs = sm + 2 * 128 * ASTR;      // [128 rows][ASTR cols]

    int tid = threadIdx.x, lane = tid & 31, warp = tid >> 5;
    int gid = lane >> 2, tig = lane & 3;
    int wm = warp >> 1, wn = warp & 1;
    long rowBase = (long)blockIdx.x * 128;

    // load A tile once (transposed to k-major, tf32)
    {
        int r = tid >> 1;
        int k0 = (tid & 1) * 64;
        const float* ap = feat + (rowBase + r) * 128 + k0;
#pragma unroll
        for (int j = 0; j < 16; j++) {
            float4 a = ld4(ap + j * 4);
            int k = k0 + j * 4;
            As[(k + 0) * ASTR + r] = tf32r(a.x);
            As[(k + 1) * ASTR + r] = tf32r(a.y);
            As[(k + 2) * ASTR + r] = tf32r(a.z);
            As[(k + 3) * ASTR + r] = tf32r(a.w);
        }
    }
    __syncthreads();

    for (int t = 0; t < 15; t++) {
        const float* B;
        if (t < 6)       B = pre_w + t * 16384;
        else if (t < 12) B = suc_w + (t - 6) * 16384;
        else if (t == 12) B = left_w;
        else if (t == 13) B = right_w;
        else              B = ctr_w;

        // load B (row-major matches [k][n] layout)
#pragma unroll
        for (int j = 0; j < 16; j++) {
            int idx = tid + j * 256;
            int k = idx >> 5, n = (idx & 31) * 4;
            float4 b = ld4(B + k * 128 + n);
            float4 c;
            c.x = tf32r(b.x); c.y = tf32r(b.y); c.z = tf32r(b.z); c.w = tf32r(b.w);
            *(float4*)(Bs + k * ASTR + n) = c;
        }
        __syncthreads();

        float acc[2][8][4];
#pragma unroll
        for (int tm = 0; tm < 2; tm++)
#pragma unroll
            for (int nt = 0; nt < 8; nt++)
#pragma unroll
                for (int j = 0; j < 4; j++) acc[tm][nt][j] = 0.f;

#pragma unroll
        for (int ks = 0; ks < 16; ks++) {
            int kk = ks * 8;
            uint32_t af[2][4];
#pragma unroll
            for (int tm = 0; tm < 2; tm++) {
                int rr = wm * 32 + tm * 16 + gid;
                const float* a0p = As + (kk + tig) * ASTR + rr;
                const float* a1p = As + (kk + tig + 4) * ASTR + rr;
                af[tm][0] = __float_as_uint(a0p[0]);
                af[tm][1] = __float_as_uint(a0p[8]);
                af[tm][2] = __float_as_uint(a1p[0]);
                af[tm][3] = __float_as_uint(a1p[8]);
            }
#pragma unroll
            for (int nt = 0; nt < 8; nt++) {
                int cc = wn * 64 + nt * 8 + gid;
                uint32_t b0 = __float_as_uint(Bs[(kk + tig) * ASTR + cc]);
                uint32_t b1 = __float_as_uint(Bs[(kk + tig + 4) * ASTR + cc]);
#pragma unroll
                for (int tm = 0; tm < 2; tm++) {
                    asm volatile(
                        "mma.sync.aligned.m16n8k8.row.col.f32.tf32.tf32.f32 "
                        "{%0,%1,%2,%3}, {%4,%5,%6,%7}, {%8,%9}, {%0,%1,%2,%3};\n"
                        : "+f"(acc[tm][nt][0]), "+f"(acc[tm][nt][1]),
                          "+f"(acc[tm][nt][2]), "+f"(acc[tm][nt][3])
                        : "r"(af[tm][0]), "r"(af[tm][1]), "r"(af[tm][2]), "r"(af[tm][3]),
                          "r"(b0), "r"(b1));
                }
            }
        }

        // stage C tile in smem
#pragma unroll
        for (int tm = 0; tm < 2; tm++) {
            int r0 = wm * 32 + tm * 16 + gid;
#pragma unroll
            for (int nt = 0; nt < 8; nt++) {
                int cc = wn * 64 + nt * 8 + tig * 2;
                *(float2*)(Cs + r0 * ASTR + cc)       = make_float2(acc[tm][nt][0], acc[tm][nt][1]);
                *(float2*)(Cs + (r0 + 8) * ASTR + cc) = make_float2(acc[tm][nt][2], acc[tm][nt][3]);
            }
        }
        __syncthreads();

        // scatter straight from smem
        if (t < 14) {
            int b = t * NBLK + blockIdx.x;
            int e0 = g_bptr[b], e1 = g_bptr[b + 1];
            for (int e = e0 + warp; e < e1; e += 8) {
                int pk = __ldg(&g_edges[e]);
                int u  = pk & 0x3FFFF;
                int vl = pk >> 18;
                float4 y = *(float4*)(Cs + vl * ASTR + lane * 4);
                redv4(temp + (long)u * 128 + lane * 4, y);
            }
        } else {
            for (int r = warp; r < 128; r += 8) {
                float4 y = *(float4*)(Cs + r * ASTR + lane * 4);
                redv4(temp + (rowBase + r) * 128 + lane * 4, y);
            }
        }
        __syncthreads();   // all Cs reads done before next type's staging
    }
}

// ---------------- post: feat = relu(gn2(relu(gn1(tmp)) @ ctr2_w) + feat_old) ----------------
__global__ __launch_bounds__(256, 2) void post_kernel(
    const float* __restrict__ tmp, float* __restrict__ feat,
    const float* __restrict__ Bw,
    const float* __restrict__ ng, const float* __restrict__ nb,
    const float* __restrict__ g2, const float* __restrict__ b2,
    float* __restrict__ dout)
{
    extern __shared__ float sm[];
    float* As = sm;                  // [128 k][ASTR rows]; later reused as C staging [row][col]
    float* Bs = sm + 128 * ASTR;     // [32 k][ASTR]

    int tid = threadIdx.x, lane = tid & 31, warp = tid >> 5;
    int gid = lane >> 2, tig = lane & 3;
    int wm = warp >> 1, wn = warp & 1;
    long rowBase = (long)blockIdx.x * 128;

    // prologue: GN(norm) + relu on input row, tf32, k-major into As
    {
        int r = tid >> 1;
        int h = (tid & 1) * 64;
        const float* xp = tmp + (rowBase + r) * 128 + h;
        float s = 0.f, sq = 0.f;
#pragma unroll
        for (int j = 0; j < 16; j++) {
            float4 a = ld4(xp + j * 4);
            s  += a.x + a.y + a.z + a.w;
            sq += a.x * a.x + a.y * a.y + a.z * a.z + a.w * a.w;
        }
        s  += __shfl_xor_sync(0xffffffffu, s, 1);
        sq += __shfl_xor_sync(0xffffffffu, sq, 1);
        float mean = s * (1.f / 128.f);
        float kinv = rsqrtf(sq * (1.f / 128.f) - mean * mean + 1e-5f);
#pragma unroll
        for (int j = 0; j < 16; j++) {
            float4 a = ld4(xp + j * 4);
            int k = h + j * 4;
            float4 gg = ld4(ng + k), bb = ld4(nb + k);
            As[(k + 0) * ASTR + r] = tf32r(fmaxf((a.x - mean) * kinv * gg.x + bb.x, 0.f));
            As[(k + 1) * ASTR + r] = tf32r(fmaxf((a.y - mean) * kinv * gg.y + bb.y, 0.f));
            As[(k + 2) * ASTR + r] = tf32r(fmaxf((a.z - mean) * kinv * gg.z + bb.z, 0.f));
            As[(k + 3) * ASTR + r] = tf32r(fmaxf((a.w - mean) * kinv * gg.w + bb.w, 0.f));
        }
    }
    __syncthreads();

    float acc[2][8][4];
#pragma unroll
    for (int tm = 0; tm < 2; tm++)
#pragma unroll
        for (int nt = 0; nt < 8; nt++)
#pragma unroll
            for (int j = 0; j < 4; j++) acc[tm][nt][j] = 0.f;

    for (int kt = 0; kt < 128; kt += 32) {
        // load B chunk
#pragma unroll
        for (int j = 0; j < 4; j++) {
            int idx = tid + j * 256;
            int k = idx >> 5, n = (idx & 31) * 4;
            float4 b = ld4(Bw + (kt + k) * 128 + n);
            float4 c;
            c.x = tf32r(b.x); c.y = tf32r(b.y); c.z = tf32r(b.z); c.w = tf32r(b.w);
            *(float4*)(Bs + k * ASTR + n) = c;
        }
        __syncthreads();

#pragma unroll
        for (int ks = 0; ks < 4; ks++) {
            int kk = kt + ks * 8;
            uint32_t af[2][4];
#pragma unroll
            for (int tm = 0; tm < 2; tm++) {
                int rr = wm * 32 + tm * 16 + gid;
                const float* a0p = As + (kk + tig) * ASTR + rr;
                const float* a1p = As + (kk + tig + 4) * ASTR + rr;
                af[tm][0] = __float_as_uint(a0p[0]);
                af[tm][1] = __float_as_uint(a0p[8]);
                af[tm][2] = __float_as_uint(a1p[0]);
                af[tm][3] = __float_as_uint(a1p[8]);
            }
#pragma unroll
            for (int nt = 0; nt < 8; nt++) {
                int cc = wn * 64 + nt * 8 + gid;
                uint32_t b0 = __float_as_uint(Bs[(ks * 8 + tig) * ASTR + cc]);
                uint32_t b1 = __float_as_uint(Bs[(ks * 8 + tig + 4) * ASTR + cc]);
#pragma unroll
                for (int tm = 0; tm < 2; tm++) {
                    asm volatile(
                        "mma.sync.aligned.m16n8k8.row.col.f32.tf32.tf32.f32 "
                        "{%0,%1,%2,%3}, {%4,%5,%6,%7}, {%8,%9}, {%0,%1,%2,%3};\n"
                        : "+f"(acc[tm][nt][0]), "+f"(acc[tm][nt][1]),
                          "+f"(acc[tm][nt][2]), "+f"(acc[tm][nt][3])
                        : "r"(af[tm][0]), "r"(af[tm][1]), "r"(af[tm][2]), "r"(af[tm][3]),
                          "r"(b0), "r"(b1));
                }
            }
        }
        __syncthreads();
    }

    // stage C into As (done with A data)
#pragma unroll
    for (int tm = 0; tm < 2; tm++) {
        int r0 = wm * 32 + tm * 16 + gid;
#pragma unroll
        for (int nt = 0; nt < 8; nt++) {
            int cc = wn * 64 + nt * 8 + tig * 2;
            *(float2*)(As + r0 * ASTR + cc)       = make_float2(acc[tm][nt][0], acc[tm][nt][1]);
            *(float2*)(As + (r0 + 8) * ASTR + cc) = make_float2(acc[tm][nt][2], acc[tm][nt][3]);
        }
    }
    __syncthreads();

    // epilogue: GN(ctr2) + residual + relu, row per warp
    for (int r = warp; r < 128; r += 8) {
        int c = lane * 4;
        float4 x = *(float4*)(As + r * ASTR + c);
        float m, k;
        gn_stats(x, m, k);
        float4 gg = ld4(g2 + c), bb = ld4(b2 + c);
        long grow = rowBase + r;
        float4 old = ld4(feat + grow * 128 + c);
        float4 o;
        o.x = fmaxf((x.x - m) * k * gg.x + bb.x + old.x, 0.f);
        o.y = fmaxf((x.y - m) * k * gg.y + bb.y + old.y, 0.f);
        o.z = fmaxf((x.z - m) * k * gg.z + bb.z + old.z, 0.f);
        o.w = fmaxf((x.w - m) * k * gg.w + bb.w + old.w, 0.f);
        *(float4*)(feat + grow * 128 + c) = o;
        if (dout && grow < NN) *(float4*)(dout + grow * 128 + c) = o;
    }
}

// ---------------- host launcher ----------------
extern "C" void kernel_launch(void* const* d_in, const int* in_sizes, int n_in,
                              void* d_out, int out_size)
{
    const float* ctrs   = (const float*)d_in[0];
    const float* feats  = (const float*)d_in[1];
    const float* w_in1  = (const float*)d_in[2];
    const float* b_in1  = (const float*)d_in[3];
    const float* w_in2  = (const float*)d_in[4];
    const float* g_in   = (const float*)d_in[5];
    const float* be_in  = (const float*)d_in[6];
    const float* w_seg1 = (const float*)d_in[7];
    const float* b_seg1 = (const float*)d_in[8];
    const float* w_seg2 = (const float*)d_in[9];
    const float* g_seg  = (const float*)d_in[10];
    const float* be_seg = (const float*)d_in[11];
    const float* ctr_w  = (const float*)d_in[12];
    const float* pre_w  = (const float*)d_in[13];
    const float* suc_w  = (const float*)d_in[14];
    const float* left_w = (const float*)d_in[15];
    const float* right_w= (const float*)d_in[16];
    const float* norm_g = (const float*)d_in[17];
    const float* norm_b = (const float*)d_in[18];
    const float* ctr2_w = (const float*)d_in[19];
    const float* ctr2_g = (const float*)d_in[20];
    const float* ctr2_b = (const float*)d_in[21];
    const int* pre_u  = (const int*)d_in[22];
    const int* pre_v  = (const int*)d_in[23];
    const int* suc_u  = (const int*)d_in[24];
    const int* suc_v  = (const int*)d_in[25];
    const int* left_u = (const int*)d_in[26];
    const int* left_v = (const int*)d_in[27];
    const int* right_u= (const int*)d_in[28];
    const int* right_v= (const int*)d_in[29];

    float *feat, *tmp, *y;
    int *cnt, *cur;
    cudaGetSymbolAddress((void**)&feat, g_feat);
    cudaGetSymbolAddress((void**)&tmp,  g_tmp);
    cudaGetSymbolAddress((void**)&y,    g_y);
    cudaGetSymbolAddress((void**)&cnt,  g_cnt);
    cudaGetSymbolAddress((void**)&cur,  g_cur);

    const int MAT = 128 * 128;
    const int SMEM_GEMM = (128 + 32) * ASTR * 4;   // 87040
    const int SMEM_FUSE = 3 * 128 * ASTR * 4;      // 208896
    const int EB = (TOTAL_E + 255) / 256;

    static bool attr_set = false;
    if (!attr_set) {
        cudaFuncSetAttribute(gemm_tf32_kernel, cudaFuncAttributeMaxDynamicSharedMemorySize, SMEM_GEMM);
        cudaFuncSetAttribute(post_kernel,      cudaFuncAttributeMaxDynamicSharedMemorySize, SMEM_GEMM);
        cudaFuncSetAttribute(fuse_kernel,      cudaFuncAttributeMaxDynamicSharedMemorySize, SMEM_FUSE);
        attr_set = true;
    }

    // ---- bucket build (graph is static; rebuilt every call, cheap) ----
    cudaMemsetAsync(cnt, 0, NBUCK * sizeof(int));
    cudaMemsetAsync(cur, 0, NBUCK * sizeof(int));
    count_kernel<<<EB, 256>>>(pre_v, suc_v, left_v, right_v);
    scan_kernel<<<1, 1024>>>();
    place_kernel<<<EB, 256>>>(pre_u, pre_v, suc_u, suc_v, left_u, left_v, right_u, right_v);

    // ---- encoders ----
    enc1_kernel<<<(NN * 32) / 256, 256>>>(ctrs, feats, w_in1, b_in1, w_seg1, b_seg1, tmp, y);
    gemm_tf32_kernel<<<NBLK, 256, SMEM_GEMM>>>(tmp, w_in2, tmp);   // in-place safe (row-local)
    gemm_tf32_kernel<<<NBLK, 256, SMEM_GEMM>>>(y,   w_seg2, y);
    enc2_kernel<<<NN / 8, 256>>>(tmp, g_in, be_in, y, g_seg, be_seg, feat);

    // ---- fuse loop ----
    for (int i = 0; i < LL; i++) {
        cudaMemsetAsync(tmp, 0, (size_t)NPAD * 128 * sizeof(float));
        fuse_kernel<<<NBLK, 256, SMEM_FUSE>>>(
            feat, tmp,
            pre_w + (size_t)i * SS * MAT, suc_w + (size_t)i * SS * MAT,
            left_w + (size_t)i * MAT, right_w + (size_t)i * MAT,
            ctr_w + (size_t)i * MAT);
        post_kernel<<<NBLK, 256, SMEM_GEMM>>>(
            tmp, feat, ctr2_w + (size_t)i * MAT,
            norm_g + i * 128, norm_b + i * 128,
            ctr2_g + i * 128, ctr2_b + i * 128,
            (i == LL - 1) ? (float*)d_out : nullptr);
    }
}

// round 4
// speedup vs baseline: 2.4277x; 1.0546x over previous
#include <cuda_runtime.h>
#include <cstdint>

#define NN 200000
#define NPAD 200064     // 1563 * 128
#define DD 128
#define EE 200000
#define EE2 20000
#define SS 6
#define LL 4
#define NBLK 1563
#define AR 136          // smem stride (floats), 136 mod 32 == 8 -> conflict-free frags
#define NTYPE 14
#define NBUCK (NTYPE * NBLK)
#define TOTAL_E (12 * EE + 2 * EE2)
#define CAP1 256        // capacity per pre/suc bucket
#define CAP2 64         // capacity per left/right bucket
#define EDGESZ (12 * NBLK * CAP1 + 2 * NBLK * CAP2)

// ---------------- device scratch ----------------
__device__ float g_feat[NPAD * DD];
__device__ float g_tmp [NPAD * DD];
__device__ float g_y   [NPAD * DD];
__device__ int   g_cnt [NBUCK];
__device__ int   g_edges[EDGESZ];

__device__ __forceinline__ float4 ld4(const float* p) { return *(const float4*)(p); }

__device__ __forceinline__ float tf32r(float x) {
    float y;
    asm("cvt.rna.tf32.f32 %0, %1;" : "=f"(y) : "f"(x));
    return y;
}

__device__ __forceinline__ float wsum(float s) {
#pragma unroll
    for (int o = 16; o; o >>= 1) s += __shfl_xor_sync(0xffffffffu, s, o);
    return s;
}

__device__ __forceinline__ void redv4(float* p, float4 y) {
    asm volatile("red.global.add.v4.f32 [%0], {%1,%2,%3,%4};"
                 :: "l"(p), "f"(y.x), "f"(y.y), "f"(y.z), "f"(y.w) : "memory");
}

#define MMA_TF32(acc, a0, a1, a2, a3, b0, b1) \
    asm volatile( \
        "mma.sync.aligned.m16n8k8.row.col.f32.tf32.tf32.f32 " \
        "{%0,%1,%2,%3}, {%4,%5,%6,%7}, {%8,%9}, {%0,%1,%2,%3};\n" \
        : "+f"((acc)[0]), "+f"((acc)[1]), "+f"((acc)[2]), "+f"((acc)[3]) \
        : "r"(a0), "r"(a1), "r"(a2), "r"(a3), "r"(b0), "r"(b1))

// ---------------- bucket build: place with atomic cursors (no scan) ----------------
__global__ void place_kernel(const int* __restrict__ pre_u, const int* __restrict__ pre_v,
                             const int* __restrict__ suc_u, const int* __restrict__ suc_v,
                             const int* __restrict__ left_u, const int* __restrict__ left_v,
                             const int* __restrict__ right_u, const int* __restrict__ right_v)
{
    int idx = blockIdx.x * 256 + threadIdx.x;
    int t, u, v;
    if (idx < 6 * EE)            { t = idx / EE; u = pre_u[idx]; v = pre_v[idx]; }
    else if (idx < 12 * EE)      { int j = idx - 6 * EE; t = idx / EE; u = suc_u[j]; v = suc_v[j]; }
    else if (idx < 12 * EE + EE2){ int j = idx - 12 * EE; t = 12; u = left_u[j]; v = left_v[j]; }
    else if (idx < TOTAL_E)      { int j = idx - 12 * EE - EE2; t = 13; u = right_u[j]; v = right_v[j]; }
    else return;
    int vb = v >> 7;
    int b = t * NBLK + vb;
    int cap  = (t < 12) ? CAP1 : CAP2;
    int base = (t < 12) ? b * CAP1 : (12 * NBLK * CAP1 + ((t - 12) * NBLK + vb) * CAP2);
    int pos = atomicAdd(&g_cnt[b], 1);
    if (pos < cap) g_edges[base + pos] = u | ((v & 127) << 18);
}

// ---------------- encoder stage 1 ----------------
__global__ __launch_bounds__(256) void enc1_kernel(
    const float* __restrict__ ctrs, const float* __restrict__ feats,
    const float* __restrict__ w_in1, const float* __restrict__ b_in1,
    const float* __restrict__ w_seg1, const float* __restrict__ b_seg1,
    float* __restrict__ h_in, float* __restrict__ h_seg)
{
    int idx = blockIdx.x * blockDim.x + threadIdx.x;
    int n = idx >> 5;
    if (n >= NN) return;
    int c = (idx & 31) * 4;

    float c0 = __ldg(&ctrs[2 * n]),  c1 = __ldg(&ctrs[2 * n + 1]);
    float f0 = __ldg(&feats[2 * n]), f1 = __ldg(&feats[2 * n + 1]);

    float4 wi0 = ld4(w_in1 + c), wi1 = ld4(w_in1 + DD + c), bi = ld4(b_in1 + c);
    float4 ws0 = ld4(w_seg1 + c), ws1 = ld4(w_seg1 + DD + c), bs = ld4(b_seg1 + c);

    float4 hi, hs;
    hi.x = fmaxf(c0 * wi0.x + c1 * wi1.x + bi.x, 0.f);
    hi.y = fmaxf(c0 * wi0.y + c1 * wi1.y + bi.y, 0.f);
    hi.z = fmaxf(c0 * wi0.z + c1 * wi1.z + bi.z, 0.f);
    hi.w = fmaxf(c0 * wi0.w + c1 * wi1.w + bi.w, 0.f);
    hs.x = fmaxf(f0 * ws0.x + f1 * ws1.x + bs.x, 0.f);
    hs.y = fmaxf(f0 * ws0.y + f1 * ws1.y + bs.y, 0.f);
    hs.z = fmaxf(f0 * ws0.z + f1 * ws1.z + bs.z, 0.f);
    hs.w = fmaxf(f0 * ws0.w + f1 * ws1.w + bs.w, 0.f);

    *(float4*)&h_in [n * DD + c] = hi;
    *(float4*)&h_seg[n * DD + c] = hs;
}

// ---------------- encoder GEMM pair: Ain = Ain@Ba; Aseg = Aseg@Bb (in-place, row-local) ----------------
__global__ __launch_bounds__(256, 2) void enc_gemm2_kernel(
    float* __restrict__ Ain, const float* __restrict__ Ba,
    float* __restrict__ Aseg, const float* __restrict__ Bb)
{
    extern __shared__ float sm[];
    float* Bs = sm;              // [128][AR]
    float* As = sm + 128 * AR;   // [32][AR]

    int tid = threadIdx.x, lane = tid & 31, warp = tid >> 5;
    int gid = lane >> 2, tig = lane & 3;
    int wm = warp >> 1, wn = warp & 1;
    long rowBase = (long)blockIdx.x * 128;

    for (int p = 0; p < 2; p++) {
        float* A = p ? Aseg : Ain;
        const float* B = p ? Bb : Ba;

        for (int i = tid; i < 128 * 32; i += 256) {
            int r = i >> 5, c = (i & 31) * 4;
            float4 b = ld4(B + r * 128 + c);
            float* d = Bs + r * AR + c;
            d[0] = tf32r(b.x); d[1] = tf32r(b.y); d[2] = tf32r(b.z); d[3] = tf32r(b.w);
        }

        float acc[2][8][4];
#pragma unroll
        for (int tm = 0; tm < 2; tm++)
#pragma unroll
            for (int nt = 0; nt < 8; nt++)
#pragma unroll
                for (int j = 0; j < 4; j++) acc[tm][nt][j] = 0.f;

        int lr = tid >> 1, lkh = (tid & 1) * 16;

        for (int kt = 0; kt < 128; kt += 32) {
            const float* ap = A + (rowBase + lr) * 128 + kt + lkh;
#pragma unroll
            for (int j = 0; j < 4; j++) {
                float4 a = ld4(ap + j * 4);
                int k0 = lkh + j * 4;
                As[(k0 + 0) * AR + lr] = tf32r(a.x);
                As[(k0 + 1) * AR + lr] = tf32r(a.y);
                As[(k0 + 2) * AR + lr] = tf32r(a.z);
                As[(k0 + 3) * AR + lr] = tf32r(a.w);
            }
            __syncthreads();

#pragma unroll
            for (int ks = 0; ks < 4; ks++) {
                uint32_t af[2][4];
#pragma unroll
                for (int tm = 0; tm < 2; tm++) {
                    int rr = wm * 32 + tm * 16 + gid;
                    const float* a0p = As + (ks * 8 + tig) * AR + rr;
                    const float* a1p = As + (ks * 8 + tig + 4) * AR + rr;
                    af[tm][0] = __float_as_uint(a0p[0]);
                    af[tm][1] = __float_as_uint(a0p[8]);
                    af[tm][2] = __float_as_uint(a1p[0]);
                    af[tm][3] = __float_as_uint(a1p[8]);
                }
#pragma unroll
                for (int nt = 0; nt < 8; nt++) {
                    int cc = wn * 64 + nt * 8 + gid;
                    uint32_t b0 = __float_as_uint(Bs[(kt + ks * 8 + tig) * AR + cc]);
                    uint32_t b1 = __float_as_uint(Bs[(kt + ks * 8 + tig + 4) * AR + cc]);
#pragma unroll
                    for (int tm = 0; tm < 2; tm++)
                        MMA_TF32(acc[tm][nt], af[tm][0], af[tm][1], af[tm][2], af[tm][3], b0, b1);
                }
            }
            __syncthreads();
        }

#pragma unroll
        for (int tm = 0; tm < 2; tm++) {
            long r0 = rowBase + wm * 32 + tm * 16 + gid;
#pragma unroll
            for (int nt = 0; nt < 8; nt++) {
                int cc = wn * 64 + nt * 8 + tig * 2;
                *(float2*)(A + r0 * 128 + cc)       = make_float2(acc[tm][nt][0], acc[tm][nt][1]);
                *(float2*)(A + (r0 + 8) * 128 + cc) = make_float2(acc[tm][nt][2], acc[tm][nt][3]);
            }
        }
        __syncthreads();
    }
}

// ---------------- GN helpers ----------------
__device__ __forceinline__ void gn_stats(float4 x, float& mean, float& kinv) {
    float s  = x.x + x.y + x.z + x.w;
    float sq = x.x * x.x + x.y * x.y + x.z * x.z + x.w * x.w;
    s  = wsum(s)  * (1.f / 128.f);
    sq = wsum(sq) * (1.f / 128.f);
    mean = s;
    float var = sq - s * s;
    kinv = rsqrtf(var + 1e-5f);
}

// enc2: feat = relu(gn(A) + gn(B)); also zero A rows (tmp) for fuse iter 0.
__global__ __launch_bounds__(256) void enc2_kernel(
    float* __restrict__ A, const float* __restrict__ gA, const float* __restrict__ bA,
    const float* __restrict__ Bv, const float* __restrict__ gB, const float* __restrict__ bB,
    float* __restrict__ feat)
{
    int row = blockIdx.x * 8 + (threadIdx.x >> 5);
    if (row >= NN) return;
    int lane = threadIdx.x & 31;
    int c = lane * 4;
    float4 a = ld4(&A[(long)row * 128 + c]);
    float4 b = ld4(&Bv[(long)row * 128 + c]);
    float ma, ka, mb, kb;
    gn_stats(a, ma, ka);
    gn_stats(b, mb, kb);
    float4 ga = ld4(gA + c), ba = ld4(bA + c);
    float4 gb = ld4(gB + c), bb = ld4(bB + c);
    float4 o;
    o.x = fmaxf((a.x - ma) * ka * ga.x + ba.x + (b.x - mb) * kb * gb.x + bb.x, 0.f);
    o.y = fmaxf((a.y - ma) * ka * ga.y + ba.y + (b.y - mb) * kb * gb.y + bb.y, 0.f);
    o.z = fmaxf((a.z - ma) * ka * ga.z + ba.z + (b.z - mb) * kb * gb.z + bb.z, 0.f);
    o.w = fmaxf((a.w - ma) * ka * ga.w + ba.w + (b.w - mb) * kb * gb.w + bb.w, 0.f);
    *(float4*)&feat[(long)row * 128 + c] = o;
    *(float4*)&A   [(long)row * 128 + c] = make_float4(0.f, 0.f, 0.f, 0.f);
}

// ---------------- fused message-passing kernel (512 threads, B reg-prefetch) ----------------
__global__ __launch_bounds__(512) void fuse_kernel(
    const float* __restrict__ feat, float* __restrict__ temp,
    const float* __restrict__ pre_w, const float* __restrict__ suc_w,
    const float* __restrict__ left_w, const float* __restrict__ right_w,
    const float* __restrict__ ctr_w)
{
    extern __shared__ float sm[];
    float* As = sm;                  // [128 k][AR rows]
    float* Bs = sm + 128 * AR;       // [128 k][AR cols]
    float* Cs = sm + 256 * AR;       // [128 rows][AR cols]

    int tid = threadIdx.x, lane = tid & 31, warp = tid >> 5;
    int gid = lane >> 2, tig = lane & 3;
    int wm = warp >> 2, wn = warp & 3;       // 4x4 warp grid, warp tile 32x32
    long rowBase = (long)blockIdx.x * 128;

    // load A tile once (k-major, tf32)
    {
        int r = tid >> 2, kq = (tid & 3) * 32;
        const float* ap = feat + (rowBase + r) * 128 + kq;
#pragma unroll
        for (int j = 0; j < 8; j++) {
            float4 a = ld4(ap + j * 4);
            int k = kq + j * 4;
            As[(k + 0) * AR + r] = tf32r(a.x);
            As[(k + 1) * AR + r] = tf32r(a.y);
            As[(k + 2) * AR + r] = tf32r(a.z);
            As[(k + 3) * AR + r] = tf32r(a.w);
        }
    }

    // prefetch B(0)
    float4 bp[8];
#pragma unroll
    for (int j = 0; j < 8; j++) bp[j] = ld4(pre_w + (tid + j * 512) * 4);

    __syncthreads();

    for (int t = 0; t < 15; t++) {
        // commit B(t) regs -> Bs (tf32)
#pragma unroll
        for (int j = 0; j < 8; j++) {
            int idx = tid + j * 512;
            int k = idx >> 5, n = (idx & 31) * 4;
            float4 c;
            c.x = tf32r(bp[j].x); c.y = tf32r(bp[j].y);
            c.z = tf32r(bp[j].z); c.w = tf32r(bp[j].w);
            *(float4*)(Bs + k * AR + n) = c;
        }
        __syncthreads();   // Bs visible; scatter(t-1) complete

        // prefetch B(t+1) (overlaps mma + scatter)
        if (t < 14) {
            int tn = t + 1;
            const float* Bn;
            if (tn < 6)       Bn = pre_w + tn * 16384;
            else if (tn < 12) Bn = suc_w + (tn - 6) * 16384;
            else if (tn == 12) Bn = left_w;
            else if (tn == 13) Bn = right_w;
            else               Bn = ctr_w;
#pragma unroll
            for (int j = 0; j < 8; j++) bp[j] = ld4(Bn + (tid + j * 512) * 4);
        }

        float acc[2][4][4];
#pragma unroll
        for (int tm = 0; tm < 2; tm++)
#pragma unroll
            for (int nt = 0; nt < 4; nt++)
#pragma unroll
                for (int j = 0; j < 4; j++) acc[tm][nt][j] = 0.f;

#pragma unroll
        for (int ks = 0; ks < 16; ks++) {
            int kk = ks * 8;
            uint32_t af[2][4];
#pragma unroll
            for (int tm = 0; tm < 2; tm++) {
                int rr = wm * 32 + tm * 16 + gid;
                const float* a0p = As + (kk + tig) * AR + rr;
                const float* a1p = As + (kk + tig + 4) * AR + rr;
                af[tm][0] = __float_as_uint(a0p[0]);
                af[tm][1] = __float_as_uint(a0p[8]);
                af[tm][2] = __float_as_uint(a1p[0]);
                af[tm][3] = __float_as_uint(a1p[8]);
            }
#pragma unroll
            for (int nt = 0; nt < 4; nt++) {
                int cc = wn * 32 + nt * 8 + gid;
                uint32_t b0 = __float_as_uint(Bs[(kk + tig) * AR + cc]);
                uint32_t b1 = __float_as_uint(Bs[(kk + tig + 4) * AR + cc]);
#pragma unroll
                for (int tm = 0; tm < 2; tm++)
                    MMA_TF32(acc[tm][nt], af[tm][0], af[tm][1], af[tm][2], af[tm][3], b0, b1);
            }
        }

        // stage C tile in smem (warp-own rows, safe pre-sync)
#pragma unroll
        for (int tm = 0; tm < 2; tm++) {
            int r0 = wm * 32 + tm * 16 + gid;
#pragma unroll
            for (int nt = 0; nt < 4; nt++) {
                int cc = wn * 32 + nt * 8 + tig * 2;
                *(float2*)(Cs + r0 * AR + cc)       = make_float2(acc[tm][nt][0], acc[tm][nt][1]);
                *(float2*)(Cs + (r0 + 8) * AR + cc) = make_float2(acc[tm][nt][2], acc[tm][nt][3]);
            }
        }
        __syncthreads();

        // scatter from smem
        if (t < 14) {
            int b = t * NBLK + blockIdx.x;
            int base = (t < 12) ? b * CAP1
                                : (12 * NBLK * CAP1 + ((t - 12) * NBLK + blockIdx.x) * CAP2);
            int cap = (t < 12) ? CAP1 : CAP2;
            int len = g_cnt[b];
            if (len > cap) len = cap;
            for (int e = warp; e < len; e += 16) {
                int pk = __ldg(&g_edges[base + e]);
                int u  = pk & 0x3FFFF;
                int vl = pk >> 18;
                float4 y = *(float4*)(Cs + vl * AR + lane * 4);
                redv4(temp + (long)u * 128 + lane * 4, y);
            }
        } else {
            for (int r = warp; r < 128; r += 16) {
                float4 y = *(float4*)(Cs + r * AR + lane * 4);
                redv4(temp + (rowBase + r) * 128 + lane * 4, y);
            }
        }
        // next iteration's B-commit writes Bs (not Cs) -> no sync needed here
    }
}

// ---------------- post: feat = relu(gn2(relu(gn1(tmp)) @ ctr2_w) + feat_old); zero tmp ----------------
__global__ __launch_bounds__(256, 2) void post_kernel(
    float* __restrict__ tmp, float* __restrict__ feat,
    const float* __restrict__ Bw,
    const float* __restrict__ ng, const float* __restrict__ nb,
    const float* __restrict__ g2, const float* __restrict__ b2,
    float* __restrict__ dout, int zero_tmp)
{
    extern __shared__ float sm[];
    float* As = sm;                  // [128 k][AR rows]; later C staging [row][col]
    float* Bs = sm + 128 * AR;       // [32 k][AR]

    int tid = threadIdx.x, lane = tid & 31, warp = tid >> 5;
    int gid = lane >> 2, tig = lane & 3;
    int wm = warp >> 1, wn = warp & 1;
    long rowBase = (long)blockIdx.x * 128;

    // prologue: GN(norm)+relu -> tf32 k-major As; zero tmp rows
    {
        int r = tid >> 1;
        int h = (tid & 1) * 64;
        float* xp = tmp + (rowBase + r) * 128 + h;
        float s = 0.f, sq = 0.f;
        float4 av[16];
#pragma unroll
        for (int j = 0; j < 16; j++) {
            av[j] = ld4(xp + j * 4);
            s  += av[j].x + av[j].y + av[j].z + av[j].w;
            sq += av[j].x * av[j].x + av[j].y * av[j].y + av[j].z * av[j].z + av[j].w * av[j].w;
        }
        s  += __shfl_xor_sync(0xffffffffu, s, 1);
        sq += __shfl_xor_sync(0xffffffffu, sq, 1);
        float mean = s * (1.f / 128.f);
        float kinv = rsqrtf(sq * (1.f / 128.f) - mean * mean + 1e-5f);
#pragma unroll
        for (int j = 0; j < 16; j++) {
            int k = h + j * 4;
            float4 gg = ld4(ng + k), bb = ld4(nb + k);
            As[(k + 0) * AR + r] = tf32r(fmaxf((av[j].x - mean) * kinv * gg.x + bb.x, 0.f));
            As[(k + 1) * AR + r] = tf32r(fmaxf((av[j].y - mean) * kinv * gg.y + bb.y, 0.f));
            As[(k + 2) * AR + r] = tf32r(fmaxf((av[j].z - mean) * kinv * gg.z + bb.z, 0.f));
            As[(k + 3) * AR + r] = tf32r(fmaxf((av[j].w - mean) * kinv * gg.w + bb.w, 0.f));
        }
        if (zero_tmp) {
            float4 z = make_float4(0.f, 0.f, 0.f, 0.f);
#pragma unroll
            for (int j = 0; j < 16; j++) *(float4*)(xp + j * 4) = z;
        }
    }
    __syncthreads();

    float acc[2][8][4];
#pragma unroll
    for (int tm = 0; tm < 2; tm++)
#pragma unroll
        for (int nt = 0; nt < 8; nt++)
#pragma unroll
            for (int j = 0; j < 4; j++) acc[tm][nt][j] = 0.f;

    for (int kt = 0; kt < 128; kt += 32) {
#pragma unroll
        for (int j = 0; j < 4; j++) {
            int idx = tid + j * 256;
            int k = idx >> 5, n = (idx & 31) * 4;
            float4 b = ld4(Bw + (kt + k) * 128 + n);
            float4 c;
            c.x = tf32r(b.x); c.y = tf32r(b.y); c.z = tf32r(b.z); c.w = tf32r(b.w);
            *(float4*)(Bs + k * AR + n) = c;
        }
        __syncthreads();

#pragma unroll
        for (int ks = 0; ks < 4; ks++) {
            int kk = kt + ks * 8;
            uint32_t af[2][4];
#pragma unroll
            for (int tm = 0; tm < 2; tm++) {
                int rr = wm * 32 + tm * 16 + gid;
                const float* a0p = As + (kk + tig) * AR + rr;
                const float* a1p = As + (kk + tig + 4) * AR + rr;
                af[tm][0] = __float_as_uint(a0p[0]);
                af[tm][1] = __float_as_uint(a0p[8]);
                af[tm][2] = __float_as_uint(a1p[0]);
                af[tm][3] = __float_as_uint(a1p[8]);
            }
#pragma unroll
            for (int nt = 0; nt < 8; nt++) {
                int cc = wn * 64 + nt * 8 + gid;
                uint32_t b0 = __float_as_uint(Bs[(ks * 8 + tig) * AR + cc]);
                uint32_t b1 = __float_as_uint(Bs[(ks * 8 + tig + 4) * AR + cc]);
#pragma unroll
                for (int tm = 0; tm < 2; tm++)
                    MMA_TF32(acc[tm][nt], af[tm][0], af[tm][1], af[tm][2], af[tm][3], b0, b1);
            }
        }
        __syncthreads();
    }

    // stage C into As
#pragma unroll
    for (int tm = 0; tm < 2; tm++) {
        int r0 = wm * 32 + tm * 16 + gid;
#pragma unroll
        for (int nt = 0; nt < 8; nt++) {
            int cc = wn * 64 + nt * 8 + tig * 2;
            *(float2*)(As + r0 * AR + cc)       = make_float2(acc[tm][nt][0], acc[tm][nt][1]);
            *(float2*)(As + (r0 + 8) * AR + cc) = make_float2(acc[tm][nt][2], acc[tm][nt][3]);
        }
    }
    __syncthreads();

    // epilogue: GN(ctr2) + residual + relu
    for (int r = warp; r < 128; r += 8) {
        int c = lane * 4;
        float4 x = *(float4*)(As + r * AR + c);
        float m, k;
        gn_stats(x, m, k);
        float4 gg = ld4(g2 + c), bb = ld4(b2 + c);
        long grow = rowBase + r;
        float4 old = ld4(feat + grow * 128 + c);
        float4 o;
        o.x = fmaxf((x.x - m) * k * gg.x + bb.x + old.x, 0.f);
        o.y = fmaxf((x.y - m) * k * gg.y + bb.y + old.y, 0.f);
        o.z = fmaxf((x.z - m) * k * gg.z + bb.z + old.z, 0.f);
        o.w = fmaxf((x.w - m) * k * gg.w + bb.w + old.w, 0.f);
        *(float4*)(feat + grow * 128 + c) = o;
        if (dout && grow < NN) *(float4*)(dout + grow * 128 + c) = o;
    }
}

// ---------------- host launcher ----------------
extern "C" void kernel_launch(void* const* d_in, const int* in_sizes, int n_in,
                              void* d_out, int out_size)
{
    const float* ctrs   = (const float*)d_in[0];
    const float* feats  = (const float*)d_in[1];
    const float* w_in1  = (const float*)d_in[2];
    const float* b_in1  = (const float*)d_in[3];
    const float* w_in2  = (const float*)d_in[4];
    const float* g_in   = (const float*)d_in[5];
    const float* be_in  = (const float*)d_in[6];
    const float* w_seg1 = (const float*)d_in[7];
    const float* b_seg1 = (const float*)d_in[8];
    const float* w_seg2 = (const float*)d_in[9];
    const float* g_seg  = (const float*)d_in[10];
    const float* be_seg = (const float*)d_in[11];
    const float* ctr_w  = (const float*)d_in[12];
    const float* pre_w  = (const float*)d_in[13];
    const float* suc_w  = (const float*)d_in[14];
    const float* left_w = (const float*)d_in[15];
    const float* right_w= (const float*)d_in[16];
    const float* norm_g = (const float*)d_in[17];
    const float* norm_b = (const float*)d_in[18];
    const float* ctr2_w = (const float*)d_in[19];
    const float* ctr2_g = (const float*)d_in[20];
    const float* ctr2_b = (const float*)d_in[21];
    const int* pre_u  = (const int*)d_in[22];
    const int* pre_v  = (const int*)d_in[23];
    const int* suc_u  = (const int*)d_in[24];
    const int* suc_v  = (const int*)d_in[25];
    const int* left_u = (const int*)d_in[26];
    const int* left_v = (const int*)d_in[27];
    const int* right_u= (const int*)d_in[28];
    const int* right_v= (const int*)d_in[29];

    float *feat, *tmp, *y;
    int *cnt;
    cudaGetSymbolAddress((void**)&feat, g_feat);
    cudaGetSymbolAddress((void**)&tmp,  g_tmp);
    cudaGetSymbolAddress((void**)&y,    g_y);
    cudaGetSymbolAddress((void**)&cnt,  g_cnt);

    const int MAT = 128 * 128;
    const int SMEM_GEMM = 160 * AR * 4;       // 87040
    const int SMEM_FUSE = 3 * 128 * AR * 4;   // 208896
    const int EB = (TOTAL_E + 255) / 256;

    static bool attr_set = false;
    if (!attr_set) {
        cudaFuncSetAttribute(enc_gemm2_kernel, cudaFuncAttributeMaxDynamicSharedMemorySize, SMEM_GEMM);
        cudaFuncSetAttribute(post_kernel,      cudaFuncAttributeMaxDynamicSharedMemorySize, SMEM_GEMM);
        cudaFuncSetAttribute(fuse_kernel,      cudaFuncAttributeMaxDynamicSharedMemorySize, SMEM_FUSE);
        attr_set = true;
    }

    // launch 0: zero bucket counters
    cudaMemsetAsync(cnt, 0, NBUCK * sizeof(int));
    // launch 1: place edges into fixed-capacity buckets
    place_kernel<<<EB, 256>>>(pre_u, pre_v, suc_u, suc_v, left_u, left_v, right_u, right_v);
    // launch 2-4: encoders (enc2 zeroes g_tmp for iter 0)
    enc1_kernel<<<(NN * 32) / 256, 256>>>(ctrs, feats, w_in1, b_in1, w_seg1, b_seg1, tmp, y);
    enc_gemm2_kernel<<<NBLK, 256, SMEM_GEMM>>>(tmp, w_in2, y, w_seg2);
    enc2_kernel<<<NN / 8, 256>>>(tmp, g_in, be_in, y, g_seg, be_seg, feat);

    // launch 5+: fuse loop (fuse i=0 is launch #5 -> ncu profiles it)
    for (int i = 0; i < LL; i++) {
        fuse_kernel<<<NBLK, 512, SMEM_FUSE>>>(
            feat, tmp,
            pre_w + (size_t)i * SS * MAT, suc_w + (size_t)i * SS * MAT,
            left_w + (size_t)i * MAT, right_w + (size_t)i * MAT,
            ctr_w + (size_t)i * MAT);
        post_kernel<<<NBLK, 256, SMEM_GEMM>>>(
            tmp, feat, ctr2_w + (size_t)i * MAT,
            norm_g + i * 128, norm_b + i * 128,
            ctr2_g + i * 128, ctr2_b + i * 128,
            (i == LL - 1) ? (float*)d_out : nullptr,
            (i < LL - 1) ? 1 : 0);
    }
}